// round 6
// baseline (speedup 1.0000x reference)
#include <cuda_runtime.h>
#include <cuda_bf16.h>
#include <math.h>
#include <stdint.h>

// ---------------- problem constants ----------------
#define MAXB     1024
#define DIM      128
#define NCHUNKS  18
#define NSLOTS   (NCHUNKS * 2)     // per-chunk key-halves
#define K8       8                 // per-slot candidate depth
#define TOPK     5
#define RESC     10                // rescored candidates per query
#define INV_T    10.0f
#define NPADMAX  (1564 * 128)

// ---------------- device scratch ----------------
__device__ int   g_excl[MAXB];
__device__ float g_qn[MAXB * DIM];                       // normalized queries fp32
__device__ float g_pval[8 * NSLOTS * 128 * K8];
__device__ int   g_pidx[8 * NSLOTS * 128 * K8];
__device__ __nv_bfloat16 g_qh[MAXB * DIM];
__device__ __nv_bfloat16 g_kh[(size_t)NPADMAX * DIM];    // 51.2 MB

// ---------------- PTX helpers ----------------
__device__ __forceinline__ uint32_t smem_u32(const void* p) {
    uint32_t a;
    asm("{ .reg .u64 t; cvta.to.shared.u64 t, %1; cvt.u32.u64 %0, t; }" : "=r"(a) : "l"(p));
    return a;
}
__device__ __forceinline__ void cp16(uint32_t s, const void* g) {
    asm volatile("cp.async.cg.shared.global [%0], [%1], 16;" :: "r"(s), "l"(g));
}
#define CP_COMMIT()  asm volatile("cp.async.commit_group;")
#define CP_WAIT(n)   asm volatile("cp.async.wait_group %0;" :: "n"(n))

#define LDSM4(r0, r1, r2, r3, addr)                                         \
    asm volatile("ldmatrix.sync.aligned.m8n8.x4.shared.b16 {%0,%1,%2,%3}, [%4];" \
                 : "=r"(r0), "=r"(r1), "=r"(r2), "=r"(r3) : "r"(addr))

#define MMA16816(c, a, b0, b1)                                              \
    asm volatile("mma.sync.aligned.m16n8k16.row.col.f32.bf16.bf16.f32 "     \
                 "{%0,%1,%2,%3},{%4,%5,%6,%7},{%8,%9},{%0,%1,%2,%3};"       \
                 : "+f"((c)[0]), "+f"((c)[1]), "+f"((c)[2]), "+f"((c)[3])   \
                 : "r"((a)[0]), "r"((a)[1]), "r"((a)[2]), "r"((a)[3]),      \
                   "r"(b0), "r"(b1))

// ---------------- top-8 helpers (register resident) ----------------
__device__ __forceinline__ void t8_ins(float (&tv)[K8], int (&ti)[K8], float s, int idx) {
    tv[K8 - 1] = s; ti[K8 - 1] = idx;
    #pragma unroll
    for (int p = K8 - 1; p > 0; --p) {
        if (tv[p] > tv[p - 1]) {
            float fv = tv[p]; tv[p] = tv[p - 1]; tv[p - 1] = fv;
            int fi = ti[p]; ti[p] = ti[p - 1]; ti[p - 1] = fi;
        }
    }
}
__device__ __forceinline__ void t8_merge_xor(float (&tv)[K8], int (&ti)[K8], int off) {
    float pv[K8]; int pi[K8];
    #pragma unroll
    for (int r = 0; r < K8; ++r) {
        pv[r] = __shfl_xor_sync(0xffffffffu, tv[r], off);
        pi[r] = __shfl_xor_sync(0xffffffffu, ti[r], off);
    }
    #pragma unroll
    for (int r = 0; r < K8; ++r)
        if (pv[r] > tv[K8 - 1]) t8_ins(tv, ti, pv[r], pi[r]);
}

// ---------------- kernel: normalize queries (fp32 + bf16-hi) ----------------
__global__ void prep_q(const float* __restrict__ q, int B) {
    int w = (blockIdx.x * blockDim.x + threadIdx.x) >> 5;
    int lane = threadIdx.x & 31;
    if (w >= B) return;
    float4 v = *(const float4*)(q + (size_t)w * DIM + lane * 4);
    float ss = v.x * v.x + v.y * v.y + v.z * v.z + v.w * v.w;
    #pragma unroll
    for (int o = 16; o; o >>= 1) ss += __shfl_xor_sync(0xffffffffu, ss, o);
    float sc = 1.0f / fmaxf(sqrtf(ss), 1e-12f);
    float4 r = make_float4(v.x * sc, v.y * sc, v.z * sc, v.w * sc);
    size_t off = (size_t)w * DIM + lane * 4;
    *(float4*)(g_qn + off) = r;
    __nv_bfloat162 h0 = __floats2bfloat162_rn(r.x, r.y);
    __nv_bfloat162 h1 = __floats2bfloat162_rn(r.z, r.w);
    *(uint2*)(g_qh + off) = make_uint2(*(uint32_t*)&h0, *(uint32_t*)&h1);
}

// ---------------- kernel: decode exclude (int32/int64 sniff) ----------------
__global__ void decode_exclude(const void* __restrict__ ex, int B) {
    __shared__ int nz;
    int t = threadIdx.x;
    if (t == 0) nz = 0;
    __syncthreads();
    const int* e32 = (const int*)ex;
    if (t < B / 2) { if (e32[2 * t + 1] != 0) atomicAdd(&nz, 1); }
    __syncthreads();
    bool is64 = (nz == 0);
    if (t < B) {
        long long v = is64 ? ((const long long*)ex)[t] : (long long)e32[t];
        g_excl[t] = (int)v;
    }
}

// ---------------- kernel: fp32 memory -> bf16 hi ----------------
__global__ void split_mem(const float* __restrict__ mem, int N, int NPAD) {
    int total4 = NPAD * (DIM / 4);
    for (int i = blockIdx.x * blockDim.x + threadIdx.x; i < total4;
         i += gridDim.x * blockDim.x) {
        int row = i >> 5;
        float4 v = make_float4(0.f, 0.f, 0.f, 0.f);
        if (row < N) v = ((const float4*)mem)[i];
        __nv_bfloat162 h0 = __floats2bfloat162_rn(v.x, v.y);
        __nv_bfloat162 h1 = __floats2bfloat162_rn(v.z, v.w);
        ((uint2*)g_kh)[i] = make_uint2(*(uint32_t*)&h0, *(uint32_t*)&h1);
    }
}

// ---------------- key tile loader (XOR-swizzled rows for ldmatrix) ----------
// 128 rows x 256B. row r, 16B chunk c: off = r*256 + ((c ^ (r&7)) << 4)
__device__ __forceinline__ void load_ktile(uint32_t stage_u, int key0, bool valid, int tid) {
    if (valid) {
        #pragma unroll
        for (int c = tid; c < 2048; c += 512) {
            int row = c >> 4, ch = c & 15;
            uint32_t off = (uint32_t)(row * 256 + (((ch ^ (row & 7))) << 4));
            cp16(stage_u + off, g_kh + (size_t)(key0 + row) * DIM + ch * 8);
        }
    }
    CP_COMMIT();
}

// ---------------- main filter kernel: approx sims + streaming top-8 ---------
__global__ void __launch_bounds__(512, 1)
sim_topk(int N, int Ntiles) {
    extern __shared__ __align__(16) char sm[];
    uint32_t smb = smem_u32(sm);
    uint32_t stage_u = (smb + 1023u) & ~1023u;

    int tid = threadIdx.x;
    int wid = tid >> 5;
    int lane = tid & 31;
    int wq = wid & 7;            // query-row group
    int khalf = wid >> 3;        // key half
    int qbase = blockIdx.x * 128;
    int chunk = blockIdx.y;

    int TPC = (Ntiles + NCHUNKS - 1) / NCHUNKS;
    int t0 = chunk * TPC;
    int T = min(TPC, Ntiles - t0); if (T < 0) T = 0;

    load_ktile(stage_u,         (t0 + 0) * 128, 0 < T, tid);
    load_ktile(stage_u + 32768, (t0 + 1) * 128, 1 < T, tid);

    // preload A fragments (bf16-hi of this warp's 16 query rows)
    int qr = qbase + wq * 16 + (lane >> 2);
    const __nv_bfloat16* qhp = g_qh + (size_t)qr * DIM;
    uint32_t ah[8][4];
    #pragma unroll
    for (int kc = 0; kc < 8; ++kc) {
        int c = kc * 16 + (lane & 3) * 2;
        ah[kc][0] = *(const uint32_t*)(qhp + c);
        ah[kc][1] = *(const uint32_t*)(qhp + 8 * DIM + c);
        ah[kc][2] = *(const uint32_t*)(qhp + c + 8);
        ah[kc][3] = *(const uint32_t*)(qhp + 8 * DIM + c + 8);
    }

    float tv0[K8], tv1[K8]; int ti0[K8], ti1[K8];
    #pragma unroll
    for (int r = 0; r < K8; ++r) {
        tv0[r] = -INFINITY; ti0[r] = -1;
        tv1[r] = -INFINITY; ti1[r] = -1;
    }

    int r_   = lane & 7;
    int cbit = (lane >> 3) & 1;
    int kb256 = (khalf << 14) + ((lane >> 4) * 8 + r_) * 256;

    for (int t = 0; t < T; ++t) {
        CP_WAIT(1);
        __syncthreads();

        load_ktile(stage_u + ((t + 2) % 3) * 32768, (t0 + t + 2) * 128,
                   (t + 2) < T, tid);

        uint32_t st = stage_u + (t % 3) * 32768;

        float acc[8][4];
        #pragma unroll
        for (int nb = 0; nb < 8; ++nb)
            #pragma unroll
            for (int j = 0; j < 4; ++j) acc[nb][j] = 0.f;

        #pragma unroll
        for (int kc = 0; kc < 8; ++kc) {
            uint32_t ch = (uint32_t)(((kc * 2 + cbit) ^ r_) << 4);
            uint32_t base_h = st + kb256 + ch;
            #pragma unroll
            for (int nbp = 0; nbp < 4; ++nbp) {
                uint32_t bh0, bh1, bh2, bh3;
                LDSM4(bh0, bh1, bh2, bh3, base_h + nbp * 4096);
                MMA16816(acc[2 * nbp],     ah[kc], bh0, bh1);
                MMA16816(acc[2 * nbp + 1], ah[kc], bh2, bh3);
            }
        }

        // ---- streaming top-8 scan: cheap guarded fast path, no index math,
        // no bounds/exclusion checks (pad keys & exclude filtered in merge).
        int c0 = (t0 + t) * 128 + khalf * 64 + (lane & 3) * 2;
        #pragma unroll
        for (int nb = 0; nb < 8; ++nb) {
            float s0 = acc[nb][0], s1 = acc[nb][1];
            if (__builtin_expect(fmaxf(s0, s1) > tv0[K8 - 1], 0)) {
                int kg = c0 + nb * 8;
                if (s0 > tv0[K8 - 1]) t8_ins(tv0, ti0, s0, kg);
                if (s1 > tv0[K8 - 1]) t8_ins(tv0, ti0, s1, kg + 1);
            }
            float s2 = acc[nb][2], s3 = acc[nb][3];
            if (__builtin_expect(fmaxf(s2, s3) > tv1[K8 - 1], 0)) {
                int kg = c0 + nb * 8;
                if (s2 > tv1[K8 - 1]) t8_ins(tv1, ti1, s2, kg);
                if (s3 > tv1[K8 - 1]) t8_ins(tv1, ti1, s3, kg + 1);
            }
        }
    }

    CP_WAIT(0);

    // merge across the 4 lanes sharing each query row
    t8_merge_xor(tv0, ti0, 1); t8_merge_xor(tv0, ti0, 2);
    t8_merge_xor(tv1, ti1, 1); t8_merge_xor(tv1, ti1, 2);

    if ((lane & 3) == 0) {
        int row0 = wq * 16 + (lane >> 2);
        size_t slot = (size_t)((blockIdx.x * NCHUNKS + chunk) * 2 + khalf) * 128;
        size_t b0 = (slot + row0) * K8;
        size_t b1 = (slot + row0 + 8) * K8;
        #pragma unroll
        for (int r = 0; r < K8; ++r) {
            g_pval[b0 + r] = tv0[r]; g_pidx[b0 + r] = ti0[r];
            g_pval[b1 + r] = tv1[r]; g_pidx[b1 + r] = ti1[r];
        }
    }
}

// ---------------- merge + exact rescore + softmax/gather/normalize ----------
__global__ void merge_out(const float* __restrict__ mem, float* __restrict__ out,
                          int N, int B) {
    int q = (blockIdx.x * blockDim.x + threadIdx.x) >> 5;
    int lane = threadIdx.x & 31;
    if (q >= B) return;
    int qtile = q >> 7, ql = q & 127;
    int exq = g_excl[q];

    // ---- phase 1: approx top-RESC of 288 candidates (9 per lane),
    // filtering pad keys (ci >= N) and the exclude index here.
    float cv[9]; int ci[9];
    #pragma unroll
    for (int s = 0; s < 9; ++s) {
        int cidx = lane + 32 * s;                       // < 288 always
        int c = cidx / K8, r = cidx % K8;
        size_t base = ((size_t)(qtile * NSLOTS + c) * 128 + ql) * K8 + r;
        float v = g_pval[base]; int id = g_pidx[base];
        if ((unsigned)id >= (unsigned)N || id == exq) v = -INFINITY;
        cv[s] = v; ci[s] = id;
    }

    int ridx[RESC];
    #pragma unroll
    for (int k = 0; k < RESC; ++k) {
        float bv = cv[0]; int bi = ci[0];
        #pragma unroll
        for (int s = 1; s < 9; ++s)
            if (cv[s] > bv || (cv[s] == bv && ci[s] < bi)) { bv = cv[s]; bi = ci[s]; }
        #pragma unroll
        for (int o = 16; o; o >>= 1) {
            float ov = __shfl_xor_sync(0xffffffffu, bv, o);
            int   oi = __shfl_xor_sync(0xffffffffu, bi, o);
            if (ov > bv || (ov == bv && oi < bi)) { bv = ov; bi = oi; }
        }
        ridx[k] = (bi < 0 || bi >= N) ? 0 : bi;   // safety clamp
        #pragma unroll
        for (int s = 0; s < 9; ++s) if (ci[s] == bi) cv[s] = -INFINITY;
    }

    // ---- phase 2: exact fp32 rescore of the RESC survivors
    float4 qv = *(const float4*)(g_qn + (size_t)q * DIM + lane * 4);
    float rv[RESC];
    #pragma unroll
    for (int k = 0; k < RESC; ++k) {
        float4 m4 = *(const float4*)(mem + (size_t)ridx[k] * DIM + lane * 4);
        float d = qv.x * m4.x + qv.y * m4.y + qv.z * m4.z + qv.w * m4.w;
        #pragma unroll
        for (int o = 16; o; o >>= 1) d += __shfl_xor_sync(0xffffffffu, d, o);
        rv[k] = d;
    }

    // ---- phase 3: exact top-5 (lower index wins ties), all lanes redundant
    float tv[TOPK]; int ti[TOPK];
    int usedmask = 0;
    #pragma unroll
    for (int k = 0; k < TOPK; ++k) {
        float bv = -INFINITY; int bi = 0x7fffffff, bs = -1;
        #pragma unroll
        for (int r = 0; r < RESC; ++r)
            if (!((usedmask >> r) & 1) &&
                (rv[r] > bv || (rv[r] == bv && ridx[r] < bi))) {
                bv = rv[r]; bi = ridx[r]; bs = r;
            }
        usedmask |= 1 << bs;
        tv[k] = bv; ti[k] = bi;
    }

    // ---- softmax over exact top sims
    float e[TOPK], ssum = 0.f;
    #pragma unroll
    for (int k = 0; k < TOPK; ++k) { e[k] = expf((tv[k] - tv[0]) * INV_T); ssum += e[k]; }
    float w[TOPK];
    #pragma unroll
    for (int k = 0; k < TOPK; ++k) w[k] = e[k] / ssum;

    // ---- weighted gather + renormalize
    int d0 = lane * 4;
    float4 a = make_float4(0.f, 0.f, 0.f, 0.f);
    #pragma unroll
    for (int k = 0; k < TOPK; ++k) {
        float4 m4 = *(const float4*)(mem + (size_t)ti[k] * DIM + d0);
        a.x += w[k] * m4.x; a.y += w[k] * m4.y; a.z += w[k] * m4.z; a.w += w[k] * m4.w;
    }
    float ss = a.x * a.x + a.y * a.y + a.z * a.z + a.w * a.w;
    #pragma unroll
    for (int o = 16; o; o >>= 1) ss += __shfl_xor_sync(0xffffffffu, ss, o);
    float sc = 1.0f / fmaxf(sqrtf(ss), 1e-12f);
    float4 r4 = make_float4(a.x * sc, a.y * sc, a.z * sc, a.w * sc);
    *(float4*)(out + (size_t)q * DIM + d0) = r4;

    if (lane == 0) {
        out[(size_t)B * DIM + q] = 1.0f - tv[0];
        #pragma unroll
        for (int k = 0; k < TOPK; ++k)
            out[(size_t)B * DIM + B + (size_t)q * TOPK + k] = w[k];
    }
}

// ---------------- launch ----------------
extern "C" void kernel_launch(void* const* d_in, const int* in_sizes, int n_in,
                              void* d_out, int out_size) {
    const float* query  = (const float*)d_in[0];
    const float* memory = (const float*)d_in[1];
    const void*  excl   = d_in[3];
    int B = in_sizes[0] / DIM;              // 1024
    int N = in_sizes[1] / DIM;              // 200000
    int Ntiles = (N + 127) / 128;           // 1563
    int NPAD = Ntiles * 128;
    float* out = (float*)d_out;

    prep_q<<<(B * 32 + 255) / 256, 256>>>(query, B);
    decode_exclude<<<1, 1024>>>(excl, B);
    split_mem<<<2048, 256>>>(memory, N, NPAD);

    const int SMEM = 3 * 32768 + 1024;      // 99,328 B
    cudaFuncSetAttribute(sim_topk, cudaFuncAttributeMaxDynamicSharedMemorySize, SMEM);
    sim_topk<<<dim3(B / 128, NCHUNKS), 512, SMEM>>>(N, Ntiles);

    merge_out<<<(B * 32 + 255) / 256, 256>>>(memory, out, N, B);
}

// round 7
// speedup vs baseline: 1.0697x; 1.0697x over previous
#include <cuda_runtime.h>
#include <cuda_bf16.h>
#include <math.h>
#include <stdint.h>

// ---------------- problem constants ----------------
#define MAXB     1024
#define DIM      128
#define NCHUNKS  18
#define NSLOTS   (NCHUNKS * 2)     // per-chunk key-halves
#define K8       8                 // per-slot candidate depth
#define TOPK     5
#define RESC     10                // rescored candidates per query
#define INV_T    10.0f
#define NPADMAX  (1564 * 128)

// ---------------- device scratch ----------------
__device__ int   g_excl[MAXB];
__device__ float g_qn[MAXB * DIM];                       // normalized queries fp32
__device__ float g_pval[8 * NSLOTS * 128 * K8];
__device__ int   g_pidx[8 * NSLOTS * 128 * K8];
__device__ __nv_bfloat16 g_qh[MAXB * DIM];
__device__ __nv_bfloat16 g_kh[(size_t)NPADMAX * DIM];    // 51.2 MB

// ---------------- PTX helpers ----------------
__device__ __forceinline__ uint32_t smem_u32(const void* p) {
    uint32_t a;
    asm("{ .reg .u64 t; cvta.to.shared.u64 t, %1; cvt.u32.u64 %0, t; }" : "=r"(a) : "l"(p));
    return a;
}
__device__ __forceinline__ void cp16(uint32_t s, const void* g) {
    asm volatile("cp.async.cg.shared.global [%0], [%1], 16;" :: "r"(s), "l"(g));
}
#define CP_COMMIT()  asm volatile("cp.async.commit_group;")
#define CP_WAIT(n)   asm volatile("cp.async.wait_group %0;" :: "n"(n))

#define LDSM4(r0, r1, r2, r3, addr)                                         \
    asm volatile("ldmatrix.sync.aligned.m8n8.x4.shared.b16 {%0,%1,%2,%3}, [%4];" \
                 : "=r"(r0), "=r"(r1), "=r"(r2), "=r"(r3) : "r"(addr))

#define MMA16816(c, a, b0, b1)                                              \
    asm volatile("mma.sync.aligned.m16n8k16.row.col.f32.bf16.bf16.f32 "     \
                 "{%0,%1,%2,%3},{%4,%5,%6,%7},{%8,%9},{%0,%1,%2,%3};"       \
                 : "+f"((c)[0]), "+f"((c)[1]), "+f"((c)[2]), "+f"((c)[3])   \
                 : "r"((a)[0]), "r"((a)[1]), "r"((a)[2]), "r"((a)[3]),      \
                   "r"(b0), "r"(b1))

// ---------------- top-8 helpers (register resident) ----------------
__device__ __forceinline__ void t8_ins(float (&tv)[K8], int (&ti)[K8], float s, int idx) {
    tv[K8 - 1] = s; ti[K8 - 1] = idx;
    #pragma unroll
    for (int p = K8 - 1; p > 0; --p) {
        if (tv[p] > tv[p - 1]) {
            float fv = tv[p]; tv[p] = tv[p - 1]; tv[p - 1] = fv;
            int fi = ti[p]; ti[p] = ti[p - 1]; ti[p - 1] = fi;
        }
    }
}
__device__ __forceinline__ void t8_merge_xor(float (&tv)[K8], int (&ti)[K8], int off) {
    float pv[K8]; int pi[K8];
    #pragma unroll
    for (int r = 0; r < K8; ++r) {
        pv[r] = __shfl_xor_sync(0xffffffffu, tv[r], off);
        pi[r] = __shfl_xor_sync(0xffffffffu, ti[r], off);
    }
    #pragma unroll
    for (int r = 0; r < K8; ++r)
        if (pv[r] > tv[K8 - 1]) t8_ins(tv, ti, pv[r], pi[r]);
}

// ---------------- kernel: normalize queries (fp32 + bf16-hi) ----------------
__global__ void prep_q(const float* __restrict__ q, int B) {
    int w = (blockIdx.x * blockDim.x + threadIdx.x) >> 5;
    int lane = threadIdx.x & 31;
    if (w >= B) return;
    float4 v = *(const float4*)(q + (size_t)w * DIM + lane * 4);
    float ss = v.x * v.x + v.y * v.y + v.z * v.z + v.w * v.w;
    #pragma unroll
    for (int o = 16; o; o >>= 1) ss += __shfl_xor_sync(0xffffffffu, ss, o);
    float sc = 1.0f / fmaxf(sqrtf(ss), 1e-12f);
    float4 r = make_float4(v.x * sc, v.y * sc, v.z * sc, v.w * sc);
    size_t off = (size_t)w * DIM + lane * 4;
    *(float4*)(g_qn + off) = r;
    __nv_bfloat162 h0 = __floats2bfloat162_rn(r.x, r.y);
    __nv_bfloat162 h1 = __floats2bfloat162_rn(r.z, r.w);
    *(uint2*)(g_qh + off) = make_uint2(*(uint32_t*)&h0, *(uint32_t*)&h1);
}

// ---------------- kernel: decode exclude (int32/int64 sniff) ----------------
__global__ void decode_exclude(const void* __restrict__ ex, int B) {
    __shared__ int nz;
    int t = threadIdx.x;
    if (t == 0) nz = 0;
    __syncthreads();
    const int* e32 = (const int*)ex;
    if (t < B / 2) { if (e32[2 * t + 1] != 0) atomicAdd(&nz, 1); }
    __syncthreads();
    bool is64 = (nz == 0);
    if (t < B) {
        long long v = is64 ? ((const long long*)ex)[t] : (long long)e32[t];
        g_excl[t] = (int)v;
    }
}

// ---------------- kernel: fp32 memory -> bf16 hi ----------------
__global__ void split_mem(const float* __restrict__ mem, int N, int NPAD) {
    int total4 = NPAD * (DIM / 4);
    for (int i = blockIdx.x * blockDim.x + threadIdx.x; i < total4;
         i += gridDim.x * blockDim.x) {
        int row = i >> 5;
        float4 v = make_float4(0.f, 0.f, 0.f, 0.f);
        if (row < N) v = ((const float4*)mem)[i];
        __nv_bfloat162 h0 = __floats2bfloat162_rn(v.x, v.y);
        __nv_bfloat162 h1 = __floats2bfloat162_rn(v.z, v.w);
        ((uint2*)g_kh)[i] = make_uint2(*(uint32_t*)&h0, *(uint32_t*)&h1);
    }
}

// ---------------- key tile loader (XOR-swizzled rows for ldmatrix) ----------
// 128 rows x 256B. row r, 16B chunk c: off = r*256 + ((c ^ (r&7)) << 4)
__device__ __forceinline__ void load_ktile(uint32_t stage_u, int key0, bool valid, int tid) {
    if (valid) {
        #pragma unroll
        for (int c = tid; c < 2048; c += 512) {
            int row = c >> 4, ch = c & 15;
            uint32_t off = (uint32_t)(row * 256 + (((ch ^ (row & 7))) << 4));
            cp16(stage_u + off, g_kh + (size_t)(key0 + row) * DIM + ch * 8);
        }
    }
    CP_COMMIT();
}

// ---------------- main filter kernel: approx sims + streaming top-8 ---------
__global__ void __launch_bounds__(512, 1)
sim_topk(int N, int Ntiles) {
    extern __shared__ __align__(16) char sm[];
    uint32_t smb = smem_u32(sm);
    uint32_t stage_u = (smb + 1023u) & ~1023u;

    int tid = threadIdx.x;
    int wid = tid >> 5;
    int lane = tid & 31;
    int wq = wid & 7;            // query-row group
    int khalf = wid >> 3;        // key half
    int qbase = blockIdx.x * 128;
    int chunk = blockIdx.y;

    int TPC = (Ntiles + NCHUNKS - 1) / NCHUNKS;
    int t0 = chunk * TPC;
    int T = min(TPC, Ntiles - t0); if (T < 0) T = 0;

    load_ktile(stage_u,         (t0 + 0) * 128, 0 < T, tid);
    load_ktile(stage_u + 32768, (t0 + 1) * 128, 1 < T, tid);

    // preload A fragments (bf16-hi of this warp's 16 query rows)
    int qr = qbase + wq * 16 + (lane >> 2);
    const __nv_bfloat16* qhp = g_qh + (size_t)qr * DIM;
    uint32_t ah[8][4];
    #pragma unroll
    for (int kc = 0; kc < 8; ++kc) {
        int c = kc * 16 + (lane & 3) * 2;
        ah[kc][0] = *(const uint32_t*)(qhp + c);
        ah[kc][1] = *(const uint32_t*)(qhp + 8 * DIM + c);
        ah[kc][2] = *(const uint32_t*)(qhp + c + 8);
        ah[kc][3] = *(const uint32_t*)(qhp + 8 * DIM + c + 8);
    }

    float tv0[K8], tv1[K8]; int ti0[K8], ti1[K8];
    #pragma unroll
    for (int r = 0; r < K8; ++r) {
        tv0[r] = -INFINITY; ti0[r] = -1;
        tv1[r] = -INFINITY; ti1[r] = -1;
    }

    int r_   = lane & 7;
    int cbit = (lane >> 3) & 1;
    int kb256 = (khalf << 14) + ((lane >> 4) * 8 + r_) * 256;

    // rotating stage offsets (avoid %3 in the loop)
    uint32_t stA = stage_u, stB = stage_u + 32768, stC = stage_u + 65536;

    for (int t = 0; t < T; ++t) {
        CP_WAIT(1);
        __syncthreads();

        // prefetch tile t+2 into the stage retired at t-1
        load_ktile(stC, (t0 + t + 2) * 128, (t + 2) < T, tid);

        uint32_t st = stA;

        float acc[8][4];
        #pragma unroll
        for (int nb = 0; nb < 8; ++nb)
            #pragma unroll
            for (int j = 0; j < 4; ++j) acc[nb][j] = 0.f;

        #pragma unroll
        for (int kc = 0; kc < 8; ++kc) {
            uint32_t ch = (uint32_t)(((kc * 2 + cbit) ^ r_) << 4);
            uint32_t base_h = st + kb256 + ch;
            #pragma unroll
            for (int nbp = 0; nbp < 4; ++nbp) {
                uint32_t bh0, bh1, bh2, bh3;
                LDSM4(bh0, bh1, bh2, bh3, base_h + nbp * 4096);
                MMA16816(acc[2 * nbp],     ah[kc], bh0, bh1);
                MMA16816(acc[2 * nbp + 1], ah[kc], bh2, bh3);
            }
        }

        // ---- max-tree scan: one compare per list per tile in the common path
        float m0a = fmaxf(fmaxf(acc[0][0], acc[0][1]), fmaxf(acc[1][0], acc[1][1]));
        float m0b = fmaxf(fmaxf(acc[2][0], acc[2][1]), fmaxf(acc[3][0], acc[3][1]));
        float m0c = fmaxf(fmaxf(acc[4][0], acc[4][1]), fmaxf(acc[5][0], acc[5][1]));
        float m0d = fmaxf(fmaxf(acc[6][0], acc[6][1]), fmaxf(acc[7][0], acc[7][1]));
        float m0  = fmaxf(fmaxf(m0a, m0b), fmaxf(m0c, m0d));
        float m1a = fmaxf(fmaxf(acc[0][2], acc[0][3]), fmaxf(acc[1][2], acc[1][3]));
        float m1b = fmaxf(fmaxf(acc[2][2], acc[2][3]), fmaxf(acc[3][2], acc[3][3]));
        float m1c = fmaxf(fmaxf(acc[4][2], acc[4][3]), fmaxf(acc[5][2], acc[5][3]));
        float m1d = fmaxf(fmaxf(acc[6][2], acc[6][3]), fmaxf(acc[7][2], acc[7][3]));
        float m1  = fmaxf(fmaxf(m1a, m1b), fmaxf(m1c, m1d));

        if (__builtin_expect(m0 > tv0[K8 - 1], 0)) {
            int c0 = (t0 + t) * 128 + khalf * 64 + (lane & 3) * 2;
            #pragma unroll
            for (int nb = 0; nb < 8; ++nb) {
                float s0 = acc[nb][0], s1 = acc[nb][1];
                if (s0 > tv0[K8 - 1]) t8_ins(tv0, ti0, s0, c0 + nb * 8);
                if (s1 > tv0[K8 - 1]) t8_ins(tv0, ti0, s1, c0 + nb * 8 + 1);
            }
        }
        if (__builtin_expect(m1 > tv1[K8 - 1], 0)) {
            int c0 = (t0 + t) * 128 + khalf * 64 + (lane & 3) * 2;
            #pragma unroll
            for (int nb = 0; nb < 8; ++nb) {
                float s2 = acc[nb][2], s3 = acc[nb][3];
                if (s2 > tv1[K8 - 1]) t8_ins(tv1, ti1, s2, c0 + nb * 8);
                if (s3 > tv1[K8 - 1]) t8_ins(tv1, ti1, s3, c0 + nb * 8 + 1);
            }
        }

        // rotate stages: A <- B <- C <- A
        uint32_t tmp = stA; stA = stB; stB = stC; stC = tmp;
    }

    CP_WAIT(0);

    // merge across the 4 lanes sharing each query row
    t8_merge_xor(tv0, ti0, 1); t8_merge_xor(tv0, ti0, 2);
    t8_merge_xor(tv1, ti1, 1); t8_merge_xor(tv1, ti1, 2);

    if ((lane & 3) == 0) {
        int row0 = wq * 16 + (lane >> 2);
        size_t slot = (size_t)((blockIdx.x * NCHUNKS + chunk) * 2 + khalf) * 128;
        size_t b0 = (slot + row0) * K8;
        size_t b1 = (slot + row0 + 8) * K8;
        #pragma unroll
        for (int r = 0; r < K8; ++r) {
            g_pval[b0 + r] = tv0[r]; g_pidx[b0 + r] = ti0[r];
            g_pval[b1 + r] = tv1[r]; g_pidx[b1 + r] = ti1[r];
        }
    }
}

// ---------------- merge + exact rescore + softmax/gather/normalize ----------
__global__ void merge_out(const float* __restrict__ mem, float* __restrict__ out,
                          int N, int B) {
    int q = (blockIdx.x * blockDim.x + threadIdx.x) >> 5;
    int lane = threadIdx.x & 31;
    if (q >= B) return;
    int qtile = q >> 7, ql = q & 127;
    int exq = g_excl[q];

    // ---- phase 1: approx top-RESC of 288 candidates (9 per lane),
    // filtering pad keys (ci >= N) and the exclude index here.
    float cv[9]; int ci[9];
    #pragma unroll
    for (int s = 0; s < 9; ++s) {
        int cidx = lane + 32 * s;                       // < 288 always
        int c = cidx / K8, r = cidx % K8;
        size_t base = ((size_t)(qtile * NSLOTS + c) * 128 + ql) * K8 + r;
        float v = g_pval[base]; int id = g_pidx[base];
        if ((unsigned)id >= (unsigned)N || id == exq) v = -INFINITY;
        cv[s] = v; ci[s] = id;
    }

    int ridx[RESC];
    #pragma unroll
    for (int k = 0; k < RESC; ++k) {
        float bv = cv[0]; int bi = ci[0];
        #pragma unroll
        for (int s = 1; s < 9; ++s)
            if (cv[s] > bv || (cv[s] == bv && ci[s] < bi)) { bv = cv[s]; bi = ci[s]; }
        #pragma unroll
        for (int o = 16; o; o >>= 1) {
            float ov = __shfl_xor_sync(0xffffffffu, bv, o);
            int   oi = __shfl_xor_sync(0xffffffffu, bi, o);
            if (ov > bv || (ov == bv && oi < bi)) { bv = ov; bi = oi; }
        }
        ridx[k] = (bi < 0 || bi >= N) ? 0 : bi;   // safety clamp
        #pragma unroll
        for (int s = 0; s < 9; ++s) if (ci[s] == bi) cv[s] = -INFINITY;
    }

    // ---- phase 2: exact fp32 rescore of the RESC survivors
    float4 qv = *(const float4*)(g_qn + (size_t)q * DIM + lane * 4);
    float rv[RESC];
    #pragma unroll
    for (int k = 0; k < RESC; ++k) {
        float4 m4 = *(const float4*)(mem + (size_t)ridx[k] * DIM + lane * 4);
        float d = qv.x * m4.x + qv.y * m4.y + qv.z * m4.z + qv.w * m4.w;
        #pragma unroll
        for (int o = 16; o; o >>= 1) d += __shfl_xor_sync(0xffffffffu, d, o);
        rv[k] = d;
    }

    // ---- phase 3: exact top-5 (lower index wins ties), all lanes redundant
    float tv[TOPK]; int ti[TOPK];
    int usedmask = 0;
    #pragma unroll
    for (int k = 0; k < TOPK; ++k) {
        float bv = -INFINITY; int bi = 0x7fffffff, bs = -1;
        #pragma unroll
        for (int r = 0; r < RESC; ++r)
            if (!((usedmask >> r) & 1) &&
                (rv[r] > bv || (rv[r] == bv && ridx[r] < bi))) {
                bv = rv[r]; bi = ridx[r]; bs = r;
            }
        usedmask |= 1 << bs;
        tv[k] = bv; ti[k] = bi;
    }

    // ---- softmax over exact top sims
    float e[TOPK], ssum = 0.f;
    #pragma unroll
    for (int k = 0; k < TOPK; ++k) { e[k] = expf((tv[k] - tv[0]) * INV_T); ssum += e[k]; }
    float w[TOPK];
    #pragma unroll
    for (int k = 0; k < TOPK; ++k) w[k] = e[k] / ssum;

    // ---- weighted gather + renormalize
    int d0 = lane * 4;
    float4 a = make_float4(0.f, 0.f, 0.f, 0.f);
    #pragma unroll
    for (int k = 0; k < TOPK; ++k) {
        float4 m4 = *(const float4*)(mem + (size_t)ti[k] * DIM + d0);
        a.x += w[k] * m4.x; a.y += w[k] * m4.y; a.z += w[k] * m4.z; a.w += w[k] * m4.w;
    }
    float ss = a.x * a.x + a.y * a.y + a.z * a.z + a.w * a.w;
    #pragma unroll
    for (int o = 16; o; o >>= 1) ss += __shfl_xor_sync(0xffffffffu, ss, o);
    float sc = 1.0f / fmaxf(sqrtf(ss), 1e-12f);
    float4 r4 = make_float4(a.x * sc, a.y * sc, a.z * sc, a.w * sc);
    *(float4*)(out + (size_t)q * DIM + d0) = r4;

    if (lane == 0) {
        out[(size_t)B * DIM + q] = 1.0f - tv[0];
        #pragma unroll
        for (int k = 0; k < TOPK; ++k)
            out[(size_t)B * DIM + B + (size_t)q * TOPK + k] = w[k];
    }
}

// ---------------- launch ----------------
extern "C" void kernel_launch(void* const* d_in, const int* in_sizes, int n_in,
                              void* d_out, int out_size) {
    const float* query  = (const float*)d_in[0];
    const float* memory = (const float*)d_in[1];
    const void*  excl   = d_in[3];
    int B = in_sizes[0] / DIM;              // 1024
    int N = in_sizes[1] / DIM;              // 200000
    int Ntiles = (N + 127) / 128;           // 1563
    int NPAD = Ntiles * 128;
    float* out = (float*)d_out;

    prep_q<<<(B * 32 + 255) / 256, 256>>>(query, B);
    decode_exclude<<<1, 1024>>>(excl, B);
    split_mem<<<2048, 256>>>(memory, N, NPAD);

    const int SMEM = 3 * 32768 + 1024;      // 99,328 B
    cudaFuncSetAttribute(sim_topk, cudaFuncAttributeMaxDynamicSharedMemorySize, SMEM);
    sim_topk<<<dim3(B / 128, NCHUNKS), 512, SMEM>>>(N, Ntiles);

    merge_out<<<(B * 32 + 255) / 256, 256>>>(memory, out, N, B);
}

// round 8
// speedup vs baseline: 1.7273x; 1.6148x over previous
#include <cuda_runtime.h>
#include <cuda_bf16.h>
#include <math.h>
#include <stdint.h>

// ---------------- problem constants ----------------
#define MAXB     1024
#define DIM      128
#define NCHUNKS  18
#define NSLOTS   (NCHUNKS * 2)     // per-chunk key-halves
#define K8       8                 // stored candidate depth per slot
#define TOPK     5
#define RESC     10                // rescored candidates per query
#define INV_T    10.0f
#define NPADMAX  (1564 * 128)

// ---------------- device scratch ----------------
__device__ int   g_excl[MAXB];
__device__ float g_qn[MAXB * DIM];                       // normalized queries fp32
__device__ float g_pval[8 * NSLOTS * 128 * K8];
__device__ int   g_pidx[8 * NSLOTS * 128 * K8];
__device__ __nv_bfloat16 g_qh[MAXB * DIM];
__device__ __nv_bfloat16 g_kh[(size_t)NPADMAX * DIM];    // 51.2 MB

// ---------------- PTX helpers ----------------
__device__ __forceinline__ uint32_t smem_u32(const void* p) {
    uint32_t a;
    asm("{ .reg .u64 t; cvta.to.shared.u64 t, %1; cvt.u32.u64 %0, t; }" : "=r"(a) : "l"(p));
    return a;
}
__device__ __forceinline__ void cp16(uint32_t s, const void* g) {
    asm volatile("cp.async.cg.shared.global [%0], [%1], 16;" :: "r"(s), "l"(g));
}
#define CP_COMMIT()  asm volatile("cp.async.commit_group;")
#define CP_WAIT(n)   asm volatile("cp.async.wait_group %0;" :: "n"(n))

#define LDSM4(r0, r1, r2, r3, addr)                                         \
    asm volatile("ldmatrix.sync.aligned.m8n8.x4.shared.b16 {%0,%1,%2,%3}, [%4];" \
                 : "=r"(r0), "=r"(r1), "=r"(r2), "=r"(r3) : "r"(addr))

#define MMA16816(c, a, b0, b1)                                              \
    asm volatile("mma.sync.aligned.m16n8k16.row.col.f32.bf16.bf16.f32 "     \
                 "{%0,%1,%2,%3},{%4,%5,%6,%7},{%8,%9},{%0,%1,%2,%3};"       \
                 : "+f"((c)[0]), "+f"((c)[1]), "+f"((c)[2]), "+f"((c)[3])   \
                 : "r"((a)[0]), "r"((a)[1]), "r"((a)[2]), "r"((a)[3]),      \
                   "r"(b0), "r"(b1))

// first-k MMA: D = A*B + 0 (separate zero C input; kills acc-init MOVs)
#define MMA16816_Z(c, a, b0, b1, zr)                                        \
    asm volatile("mma.sync.aligned.m16n8k16.row.col.f32.bf16.bf16.f32 "     \
                 "{%0,%1,%2,%3},{%4,%5,%6,%7},{%8,%9},{%10,%10,%10,%10};"   \
                 : "=f"((c)[0]), "=f"((c)[1]), "=f"((c)[2]), "=f"((c)[3])   \
                 : "r"((a)[0]), "r"((a)[1]), "r"((a)[2]), "r"((a)[3]),      \
                   "r"(b0), "r"(b1), "f"(zr))

// ---------------- branchless sorted-4 insert (7 FMNMX, no indices) --------
__device__ __forceinline__ void ins4(float &a, float &b, float &c, float &d, float x) {
    float m;
    m = fmaxf(a, x); x = fminf(a, x); a = m;
    m = fmaxf(b, x); x = fminf(b, x); b = m;
    m = fmaxf(c, x); x = fminf(c, x); c = m;
    d = fmaxf(d, x);
}

// ---------------- top-8 (value,idx) helpers for the endgame merge ----------
__device__ __forceinline__ void t8_ins(float (&tv)[K8], int (&ti)[K8], float s, int idx) {
    tv[K8 - 1] = s; ti[K8 - 1] = idx;
    #pragma unroll
    for (int p = K8 - 1; p > 0; --p) {
        if (tv[p] > tv[p - 1]) {
            float fv = tv[p]; tv[p] = tv[p - 1]; tv[p - 1] = fv;
            int fi = ti[p]; ti[p] = ti[p - 1]; ti[p - 1] = fi;
        }
    }
}
__device__ __forceinline__ void t8_merge_xor(float (&tv)[K8], int (&ti)[K8], int off) {
    float pv[K8]; int pi[K8];
    #pragma unroll
    for (int r = 0; r < K8; ++r) {
        pv[r] = __shfl_xor_sync(0xffffffffu, tv[r], off);
        pi[r] = __shfl_xor_sync(0xffffffffu, ti[r], off);
    }
    #pragma unroll
    for (int r = 0; r < K8; ++r)
        if (pv[r] > tv[K8 - 1]) t8_ins(tv, ti, pv[r], pi[r]);
}

// ---------------- kernel: normalize queries (fp32 + bf16-hi) ----------------
__global__ void prep_q(const float* __restrict__ q, int B) {
    int w = (blockIdx.x * blockDim.x + threadIdx.x) >> 5;
    int lane = threadIdx.x & 31;
    if (w >= B) return;
    float4 v = *(const float4*)(q + (size_t)w * DIM + lane * 4);
    float ss = v.x * v.x + v.y * v.y + v.z * v.z + v.w * v.w;
    #pragma unroll
    for (int o = 16; o; o >>= 1) ss += __shfl_xor_sync(0xffffffffu, ss, o);
    float sc = 1.0f / fmaxf(sqrtf(ss), 1e-12f);
    float4 r = make_float4(v.x * sc, v.y * sc, v.z * sc, v.w * sc);
    size_t off = (size_t)w * DIM + lane * 4;
    *(float4*)(g_qn + off) = r;
    __nv_bfloat162 h0 = __floats2bfloat162_rn(r.x, r.y);
    __nv_bfloat162 h1 = __floats2bfloat162_rn(r.z, r.w);
    *(uint2*)(g_qh + off) = make_uint2(*(uint32_t*)&h0, *(uint32_t*)&h1);
}

// ---------------- kernel: decode exclude (int32/int64 sniff) ----------------
__global__ void decode_exclude(const void* __restrict__ ex, int B) {
    __shared__ int nz;
    int t = threadIdx.x;
    if (t == 0) nz = 0;
    __syncthreads();
    const int* e32 = (const int*)ex;
    if (t < B / 2) { if (e32[2 * t + 1] != 0) atomicAdd(&nz, 1); }
    __syncthreads();
    bool is64 = (nz == 0);
    if (t < B) {
        long long v = is64 ? ((const long long*)ex)[t] : (long long)e32[t];
        g_excl[t] = (int)v;
    }
}

// ---------------- kernel: fp32 memory -> bf16 hi ----------------
__global__ void split_mem(const float* __restrict__ mem, int N, int NPAD) {
    int total4 = NPAD * (DIM / 4);
    for (int i = blockIdx.x * blockDim.x + threadIdx.x; i < total4;
         i += gridDim.x * blockDim.x) {
        int row = i >> 5;
        float4 v = make_float4(0.f, 0.f, 0.f, 0.f);
        if (row < N) v = ((const float4*)mem)[i];
        __nv_bfloat162 h0 = __floats2bfloat162_rn(v.x, v.y);
        __nv_bfloat162 h1 = __floats2bfloat162_rn(v.z, v.w);
        ((uint2*)g_kh)[i] = make_uint2(*(uint32_t*)&h0, *(uint32_t*)&h1);
    }
}

// ---------------- key tile loader (XOR-swizzled rows for ldmatrix) ----------
__device__ __forceinline__ void load_ktile(uint32_t stage_u, int key0, bool valid, int tid) {
    if (valid) {
        #pragma unroll
        for (int c = tid; c < 2048; c += 512) {
            int row = c >> 4, ch = c & 15;
            uint32_t off = (uint32_t)(row * 256 + (((ch ^ (row & 7))) << 4));
            cp16(stage_u + off, g_kh + (size_t)(key0 + row) * DIM + ch * 8);
        }
    }
    CP_COMMIT();
}

// ---------------- main filter kernel ----------------
__global__ void __launch_bounds__(512, 1)
sim_topk(int N, int Ntiles) {
    extern __shared__ __align__(16) char sm[];
    uint32_t smb = smem_u32(sm);
    uint32_t stage_u = (smb + 1023u) & ~1023u;

    int tid = threadIdx.x;
    int wid = tid >> 5;
    int lane = tid & 31;
    int wq = wid & 7;            // query-row group
    int khalf = wid >> 3;        // key half
    int qbase = blockIdx.x * 128;
    int chunk = blockIdx.y;

    int TPC = (Ntiles + NCHUNKS - 1) / NCHUNKS;   // 87 (< 128, fits 7 bits)
    int t0 = chunk * TPC;
    int T = min(TPC, Ntiles - t0); if (T < 0) T = 0;

    load_ktile(stage_u,         (t0 + 0) * 128, 0 < T, tid);
    load_ktile(stage_u + 32768, (t0 + 1) * 128, 1 < T, tid);

    // preload A fragments (bf16-hi of this warp's 16 query rows)
    int qr = qbase + wq * 16 + (lane >> 2);
    const __nv_bfloat16* qhp = g_qh + (size_t)qr * DIM;
    uint32_t ah[8][4];
    #pragma unroll
    for (int kc = 0; kc < 8; ++kc) {
        int c = kc * 16 + (lane & 3) * 2;
        ah[kc][0] = *(const uint32_t*)(qhp + c);
        ah[kc][1] = *(const uint32_t*)(qhp + 8 * DIM + c);
        ah[kc][2] = *(const uint32_t*)(qhp + c + 8);
        ah[kc][3] = *(const uint32_t*)(qhp + 8 * DIM + c + 8);
    }

    // per-lane top-4 (index packed into low 11 mantissa bits; no idx regs)
    float a0 = -3.0e38f, a1 = -3.0e38f, a2 = -3.0e38f, a3 = -3.0e38f;   // list0
    float b0_ = -3.0e38f, b1_ = -3.0e38f, b2_ = -3.0e38f, b3_ = -3.0e38f; // list1

    int r_   = lane & 7;
    int cbit = (lane >> 3) & 1;
    int kb256 = (khalf << 14) + ((lane >> 4) * 8 + r_) * 256;

    // precompute swizzled LDSM offsets (constant across tiles)
    uint32_t off_h[8];
    #pragma unroll
    for (int kc = 0; kc < 8; ++kc)
        off_h[kc] = (uint32_t)kb256 + (uint32_t)(((kc * 2 + cbit) ^ r_) << 4);

    uint32_t stA = stage_u, stB = stage_u + 32768, stC = stage_u + 65536;
    const float fzero = 0.0f;

    for (int t = 0; t < T; ++t) {
        CP_WAIT(1);
        __syncthreads();

        load_ktile(stC, (t0 + t + 2) * 128, (t + 2) < T, tid);

        float acc[8][4];
        #pragma unroll
        for (int kc = 0; kc < 8; ++kc) {
            #pragma unroll
            for (int nbp = 0; nbp < 4; ++nbp) {
                uint32_t bh0, bh1, bh2, bh3;
                LDSM4(bh0, bh1, bh2, bh3, stA + off_h[kc] + nbp * 4096);
                if (kc == 0) {
                    MMA16816_Z(acc[2 * nbp],     ah[kc], bh0, bh1, fzero);
                    MMA16816_Z(acc[2 * nbp + 1], ah[kc], bh2, bh3, fzero);
                } else {
                    MMA16816(acc[2 * nbp],     ah[kc], bh0, bh1);
                    MMA16816(acc[2 * nbp + 1], ah[kc], bh2, bh3);
                }
            }
        }

        // ---- branchless scan: pack idx into mantissa, 7-FMNMX sorted insert
        uint32_t tb = (uint32_t)t << 4;      // bits[4:11) = tile, bits[0:4) = slot
        #pragma unroll
        for (int nb = 0; nb < 8; ++nb) {
            uint32_t s;
            s = (__float_as_uint(acc[nb][0]) & 0xFFFFF800u) | tb | (uint32_t)(nb * 2);
            ins4(a0, a1, a2, a3, __uint_as_float(s));
            s = (__float_as_uint(acc[nb][1]) & 0xFFFFF800u) | tb | (uint32_t)(nb * 2 + 1);
            ins4(a0, a1, a2, a3, __uint_as_float(s));
            s = (__float_as_uint(acc[nb][2]) & 0xFFFFF800u) | tb | (uint32_t)(nb * 2);
            ins4(b0_, b1_, b2_, b3_, __uint_as_float(s));
            s = (__float_as_uint(acc[nb][3]) & 0xFFFFF800u) | tb | (uint32_t)(nb * 2 + 1);
            ins4(b0_, b1_, b2_, b3_, __uint_as_float(s));
        }

        uint32_t tmp = stA; stA = stB; stB = stC; stC = tmp;
    }

    CP_WAIT(0);

    // ---- decode this lane's packed candidates into (value, index) pairs
    int cb = khalf * 64 + (lane & 3) * 2;   // column base within tile
    float tv0[K8], tv1[K8]; int ti0[K8], ti1[K8];
    {
        float la[4] = { a0, a1, a2, a3 };
        float lb[4] = { b0_, b1_, b2_, b3_ };
        #pragma unroll
        for (int r = 0; r < 4; ++r) {
            uint32_t u = __float_as_uint(la[r]);
            int tloc = (int)((u >> 4) & 0x7F);
            int slot = (int)(u & 0xF);
            tv0[r] = la[r];
            ti0[r] = (t0 + tloc) * 128 + cb + (slot >> 1) * 8 + (slot & 1);
            u = __float_as_uint(lb[r]);
            tloc = (int)((u >> 4) & 0x7F);
            slot = (int)(u & 0xF);
            tv1[r] = lb[r];
            ti1[r] = (t0 + tloc) * 128 + cb + (slot >> 1) * 8 + (slot & 1);
        }
        #pragma unroll
        for (int r = 4; r < K8; ++r) {
            tv0[r] = -INFINITY; ti0[r] = -1;
            tv1[r] = -INFINITY; ti1[r] = -1;
        }
    }

    // merge across the 4 lanes sharing each query row -> top-8 per slot
    t8_merge_xor(tv0, ti0, 1); t8_merge_xor(tv0, ti0, 2);
    t8_merge_xor(tv1, ti1, 1); t8_merge_xor(tv1, ti1, 2);

    if ((lane & 3) == 0) {
        int row0 = wq * 16 + (lane >> 2);
        size_t slot = (size_t)((blockIdx.x * NCHUNKS + chunk) * 2 + khalf) * 128;
        size_t b0 = (slot + row0) * K8;
        size_t b1 = (slot + row0 + 8) * K8;
        #pragma unroll
        for (int r = 0; r < K8; ++r) {
            g_pval[b0 + r] = tv0[r]; g_pidx[b0 + r] = ti0[r];
            g_pval[b1 + r] = tv1[r]; g_pidx[b1 + r] = ti1[r];
        }
    }
}

// ---------------- merge + exact rescore + softmax/gather/normalize ----------
__global__ void merge_out(const float* __restrict__ mem, float* __restrict__ out,
                          int N, int B) {
    int q = (blockIdx.x * blockDim.x + threadIdx.x) >> 5;
    int lane = threadIdx.x & 31;
    if (q >= B) return;
    int qtile = q >> 7, ql = q & 127;
    int exq = g_excl[q];

    // ---- phase 1: approx top-RESC of 288 candidates (9 per lane),
    // filtering pad keys (ci >= N) and the exclude index here.
    float cv[9]; int ci[9];
    #pragma unroll
    for (int s = 0; s < 9; ++s) {
        int cidx = lane + 32 * s;                       // < 288 always
        int c = cidx / K8, r = cidx % K8;
        size_t base = ((size_t)(qtile * NSLOTS + c) * 128 + ql) * K8 + r;
        float v = g_pval[base]; int id = g_pidx[base];
        if ((unsigned)id >= (unsigned)N || id == exq) v = -INFINITY;
        cv[s] = v; ci[s] = id;
    }

    int ridx[RESC];
    #pragma unroll
    for (int k = 0; k < RESC; ++k) {
        float bv = cv[0]; int bi = ci[0];
        #pragma unroll
        for (int s = 1; s < 9; ++s)
            if (cv[s] > bv || (cv[s] == bv && ci[s] < bi)) { bv = cv[s]; bi = ci[s]; }
        #pragma unroll
        for (int o = 16; o; o >>= 1) {
            float ov = __shfl_xor_sync(0xffffffffu, bv, o);
            int   oi = __shfl_xor_sync(0xffffffffu, bi, o);
            if (ov > bv || (ov == bv && oi < bi)) { bv = ov; bi = oi; }
        }
        ridx[k] = (bi < 0 || bi >= N) ? 0 : bi;   // safety clamp
        #pragma unroll
        for (int s = 0; s < 9; ++s) if (ci[s] == bi) cv[s] = -INFINITY;
    }

    // ---- phase 2: exact fp32 rescore of the RESC survivors
    float4 qv = *(const float4*)(g_qn + (size_t)q * DIM + lane * 4);
    float rv[RESC];
    #pragma unroll
    for (int k = 0; k < RESC; ++k) {
        float4 m4 = *(const float4*)(mem + (size_t)ridx[k] * DIM + lane * 4);
        float d = qv.x * m4.x + qv.y * m4.y + qv.z * m4.z + qv.w * m4.w;
        #pragma unroll
        for (int o = 16; o; o >>= 1) d += __shfl_xor_sync(0xffffffffu, d, o);
        rv[k] = d;
    }

    // ---- phase 3: exact top-5 (lower index wins ties), all lanes redundant
    float tv[TOPK]; int ti[TOPK];
    int usedmask = 0;
    #pragma unroll
    for (int k = 0; k < TOPK; ++k) {
        float bv = -INFINITY; int bi = 0x7fffffff, bs = -1;
        #pragma unroll
        for (int r = 0; r < RESC; ++r)
            if (!((usedmask >> r) & 1) &&
                (rv[r] > bv || (rv[r] == bv && ridx[r] < bi))) {
                bv = rv[r]; bi = ridx[r]; bs = r;
            }
        usedmask |= 1 << bs;
        tv[k] = bv; ti[k] = bi;
    }

    // ---- softmax over exact top sims
    float e[TOPK], ssum = 0.f;
    #pragma unroll
    for (int k = 0; k < TOPK; ++k) { e[k] = expf((tv[k] - tv[0]) * INV_T); ssum += e[k]; }
    float w[TOPK];
    #pragma unroll
    for (int k = 0; k < TOPK; ++k) w[k] = e[k] / ssum;

    // ---- weighted gather + renormalize
    int d0 = lane * 4;
    float4 a = make_float4(0.f, 0.f, 0.f, 0.f);
    #pragma unroll
    for (int k = 0; k < TOPK; ++k) {
        float4 m4 = *(const float4*)(mem + (size_t)ti[k] * DIM + d0);
        a.x += w[k] * m4.x; a.y += w[k] * m4.y; a.z += w[k] * m4.z; a.w += w[k] * m4.w;
    }
    float ss = a.x * a.x + a.y * a.y + a.z * a.z + a.w * a.w;
    #pragma unroll
    for (int o = 16; o; o >>= 1) ss += __shfl_xor_sync(0xffffffffu, ss, o);
    float sc = 1.0f / fmaxf(sqrtf(ss), 1e-12f);
    float4 r4 = make_float4(a.x * sc, a.y * sc, a.z * sc, a.w * sc);
    *(float4*)(out + (size_t)q * DIM + d0) = r4;

    if (lane == 0) {
        out[(size_t)B * DIM + q] = 1.0f - tv[0];
        #pragma unroll
        for (int k = 0; k < TOPK; ++k)
            out[(size_t)B * DIM + B + (size_t)q * TOPK + k] = w[k];
    }
}

// ---------------- launch ----------------
extern "C" void kernel_launch(void* const* d_in, const int* in_sizes, int n_in,
                              void* d_out, int out_size) {
    const float* query  = (const float*)d_in[0];
    const float* memory = (const float*)d_in[1];
    const void*  excl   = d_in[3];
    int B = in_sizes[0] / DIM;              // 1024
    int N = in_sizes[1] / DIM;              // 200000
    int Ntiles = (N + 127) / 128;           // 1563
    int NPAD = Ntiles * 128;
    float* out = (float*)d_out;

    prep_q<<<(B * 32 + 255) / 256, 256>>>(query, B);
    decode_exclude<<<1, 1024>>>(excl, B);
    split_mem<<<2048, 256>>>(memory, N, NPAD);

    const int SMEM = 3 * 32768 + 1024;      // 99,328 B
    cudaFuncSetAttribute(sim_topk, cudaFuncAttributeMaxDynamicSharedMemorySize, SMEM);
    sim_topk<<<dim3(B / 128, NCHUNKS), 512, SMEM>>>(N, Ntiles);

    merge_out<<<(B * 32 + 255) / 256, 256>>>(memory, out, N, B);
}

// round 9
// speedup vs baseline: 2.0365x; 1.1790x over previous
#include <cuda_runtime.h>
#include <cuda_bf16.h>
#include <math.h>
#include <stdint.h>

// ---------------- problem constants ----------------
#define MAXB     1024
#define DIM      128
#define NCHUNKS  18
#define NSLOTS   (NCHUNKS * 2)     // per-chunk key-halves
#define K8       8                 // stored candidate depth per slot
#define TOPK     5
#define RESC     10                // rescored candidates per query
#define INV_T    10.0f
#define NPADMAX  (1564 * 128)

// ---------------- device scratch ----------------
__device__ int   g_excl[MAXB];
__device__ float g_qn[MAXB * DIM];                       // normalized queries fp32
__device__ float g_pval[8 * NSLOTS * 128 * K8];
__device__ int   g_pidx[8 * NSLOTS * 128 * K8];
__device__ __nv_bfloat16 g_qh[MAXB * DIM];
__device__ __nv_bfloat16 g_kh[(size_t)NPADMAX * DIM];    // 51.2 MB

// ---------------- PTX helpers ----------------
__device__ __forceinline__ uint32_t smem_u32(const void* p) {
    uint32_t a;
    asm("{ .reg .u64 t; cvta.to.shared.u64 t, %1; cvt.u32.u64 %0, t; }" : "=r"(a) : "l"(p));
    return a;
}
__device__ __forceinline__ void cp16(uint32_t s, const void* g) {
    asm volatile("cp.async.cg.shared.global [%0], [%1], 16;" :: "r"(s), "l"(g));
}
#define CP_COMMIT()  asm volatile("cp.async.commit_group;")
#define CP_WAIT(n)   asm volatile("cp.async.wait_group %0;" :: "n"(n))

#define LDSM4(r0, r1, r2, r3, addr)                                         \
    asm volatile("ldmatrix.sync.aligned.m8n8.x4.shared.b16 {%0,%1,%2,%3}, [%4];" \
                 : "=r"(r0), "=r"(r1), "=r"(r2), "=r"(r3) : "r"(addr))

#define MMA16816(c, a, b0, b1)                                              \
    asm volatile("mma.sync.aligned.m16n8k16.row.col.f32.bf16.bf16.f32 "     \
                 "{%0,%1,%2,%3},{%4,%5,%6,%7},{%8,%9},{%0,%1,%2,%3};"       \
                 : "+f"((c)[0]), "+f"((c)[1]), "+f"((c)[2]), "+f"((c)[3])   \
                 : "r"((a)[0]), "r"((a)[1]), "r"((a)[2]), "r"((a)[3]),      \
                   "r"(b0), "r"(b1))

// first-k MMA: D = A*B + 0 (separate zero C input; kills acc-init MOVs)
#define MMA16816_Z(c, a, b0, b1, zr)                                        \
    asm volatile("mma.sync.aligned.m16n8k16.row.col.f32.bf16.bf16.f32 "     \
                 "{%0,%1,%2,%3},{%4,%5,%6,%7},{%8,%9},{%10,%10,%10,%10};"   \
                 : "=f"((c)[0]), "=f"((c)[1]), "=f"((c)[2]), "=f"((c)[3])   \
                 : "r"((a)[0]), "r"((a)[1]), "r"((a)[2]), "r"((a)[3]),      \
                   "r"(b0), "r"(b1), "f"(zr))

// ---------------- branchless sorted-3 insert (5 FMNMX, no indices) --------
__device__ __forceinline__ void ins3(float &a, float &b, float &c, float x) {
    float m;
    m = fmaxf(a, x); x = fminf(a, x); a = m;
    m = fmaxf(b, x); x = fminf(b, x); b = m;
    c = fmaxf(c, x);
}

// ---------------- top-8 (value,idx) helpers for the endgame merge ----------
__device__ __forceinline__ void t8_ins(float (&tv)[K8], int (&ti)[K8], float s, int idx) {
    tv[K8 - 1] = s; ti[K8 - 1] = idx;
    #pragma unroll
    for (int p = K8 - 1; p > 0; --p) {
        if (tv[p] > tv[p - 1]) {
            float fv = tv[p]; tv[p] = tv[p - 1]; tv[p - 1] = fv;
            int fi = ti[p]; ti[p] = ti[p - 1]; ti[p - 1] = fi;
        }
    }
}
__device__ __forceinline__ void t8_merge_xor(float (&tv)[K8], int (&ti)[K8], int off) {
    float pv[K8]; int pi[K8];
    #pragma unroll
    for (int r = 0; r < K8; ++r) {
        pv[r] = __shfl_xor_sync(0xffffffffu, tv[r], off);
        pi[r] = __shfl_xor_sync(0xffffffffu, ti[r], off);
    }
    #pragma unroll
    for (int r = 0; r < K8; ++r)
        if (pv[r] > tv[K8 - 1]) t8_ins(tv, ti, pv[r], pi[r]);
}

// ---------------- kernel: normalize queries (fp32 + bf16-hi) ----------------
__global__ void prep_q(const float* __restrict__ q, int B) {
    int w = (blockIdx.x * blockDim.x + threadIdx.x) >> 5;
    int lane = threadIdx.x & 31;
    if (w >= B) return;
    float4 v = *(const float4*)(q + (size_t)w * DIM + lane * 4);
    float ss = v.x * v.x + v.y * v.y + v.z * v.z + v.w * v.w;
    #pragma unroll
    for (int o = 16; o; o >>= 1) ss += __shfl_xor_sync(0xffffffffu, ss, o);
    float sc = 1.0f / fmaxf(sqrtf(ss), 1e-12f);
    float4 r = make_float4(v.x * sc, v.y * sc, v.z * sc, v.w * sc);
    size_t off = (size_t)w * DIM + lane * 4;
    *(float4*)(g_qn + off) = r;
    __nv_bfloat162 h0 = __floats2bfloat162_rn(r.x, r.y);
    __nv_bfloat162 h1 = __floats2bfloat162_rn(r.z, r.w);
    *(uint2*)(g_qh + off) = make_uint2(*(uint32_t*)&h0, *(uint32_t*)&h1);
}

// ---------------- kernel: decode exclude (int32/int64 sniff) ----------------
__global__ void decode_exclude(const void* __restrict__ ex, int B) {
    __shared__ int nz;
    int t = threadIdx.x;
    if (t == 0) nz = 0;
    __syncthreads();
    const int* e32 = (const int*)ex;
    if (t < B / 2) { if (e32[2 * t + 1] != 0) atomicAdd(&nz, 1); }
    __syncthreads();
    bool is64 = (nz == 0);
    if (t < B) {
        long long v = is64 ? ((const long long*)ex)[t] : (long long)e32[t];
        g_excl[t] = (int)v;
    }
}

// ---------------- kernel: fp32 memory -> bf16 hi ----------------
__global__ void split_mem(const float* __restrict__ mem, int N, int NPAD) {
    int total4 = NPAD * (DIM / 4);
    for (int i = blockIdx.x * blockDim.x + threadIdx.x; i < total4;
         i += gridDim.x * blockDim.x) {
        int row = i >> 5;
        float4 v = make_float4(0.f, 0.f, 0.f, 0.f);
        if (row < N) v = ((const float4*)mem)[i];
        __nv_bfloat162 h0 = __floats2bfloat162_rn(v.x, v.y);
        __nv_bfloat162 h1 = __floats2bfloat162_rn(v.z, v.w);
        ((uint2*)g_kh)[i] = make_uint2(*(uint32_t*)&h0, *(uint32_t*)&h1);
    }
}

// ---------------- key tile loader (XOR-swizzled rows for ldmatrix) ----------
__device__ __forceinline__ void load_ktile(uint32_t stage_u, int key0, bool valid, int tid) {
    if (valid) {
        #pragma unroll
        for (int c = tid; c < 2048; c += 512) {
            int row = c >> 4, ch = c & 15;
            uint32_t off = (uint32_t)(row * 256 + (((ch ^ (row & 7))) << 4));
            cp16(stage_u + off, g_kh + (size_t)(key0 + row) * DIM + ch * 8);
        }
    }
    CP_COMMIT();
}

// ---------------- main filter kernel ----------------
__global__ void __launch_bounds__(512, 1)
sim_topk(int N, int Ntiles) {
    extern __shared__ __align__(16) char sm[];
    uint32_t smb = smem_u32(sm);
    uint32_t stage_u = (smb + 1023u) & ~1023u;

    int tid = threadIdx.x;
    int wid = tid >> 5;
    int lane = tid & 31;
    int wq = wid & 7;            // query-row group
    int khalf = wid >> 3;        // key half
    int qbase = blockIdx.x * 128;
    int chunk = blockIdx.y;

    int TPC = (Ntiles + NCHUNKS - 1) / NCHUNKS;   // 87 (< 128, fits 7 bits)
    int t0 = chunk * TPC;
    int T = min(TPC, Ntiles - t0); if (T < 0) T = 0;

    load_ktile(stage_u,         (t0 + 0) * 128, 0 < T, tid);
    load_ktile(stage_u + 32768, (t0 + 1) * 128, 1 < T, tid);

    // preload A fragments (bf16-hi of this warp's 16 query rows)
    int qr = qbase + wq * 16 + (lane >> 2);
    const __nv_bfloat16* qhp = g_qh + (size_t)qr * DIM;
    uint32_t ah[8][4];
    #pragma unroll
    for (int kc = 0; kc < 8; ++kc) {
        int c = kc * 16 + (lane & 3) * 2;
        ah[kc][0] = *(const uint32_t*)(qhp + c);
        ah[kc][1] = *(const uint32_t*)(qhp + 8 * DIM + c);
        ah[kc][2] = *(const uint32_t*)(qhp + c + 8);
        ah[kc][3] = *(const uint32_t*)(qhp + 8 * DIM + c + 8);
    }

    // per-lane top-3 of pair-maxima (index packed into low 11 mantissa bits)
    float a0 = -3.0e38f, a1 = -3.0e38f, a2 = -3.0e38f;      // list0 (row lo)
    float b0_ = -3.0e38f, b1_ = -3.0e38f, b2_ = -3.0e38f;   // list1 (row hi)

    int r_   = lane & 7;
    int cbit = (lane >> 3) & 1;
    int kb256 = (khalf << 14) + ((lane >> 4) * 8 + r_) * 256;

    // precompute swizzled LDSM offsets (constant across tiles)
    uint32_t off_h[8];
    #pragma unroll
    for (int kc = 0; kc < 8; ++kc)
        off_h[kc] = (uint32_t)kb256 + (uint32_t)(((kc * 2 + cbit) ^ r_) << 4);

    uint32_t stA = stage_u, stB = stage_u + 32768, stC = stage_u + 65536;
    const float fzero = 0.0f;

    for (int t = 0; t < T; ++t) {
        CP_WAIT(1);
        __syncthreads();

        load_ktile(stC, (t0 + t + 2) * 128, (t + 2) < T, tid);

        float acc[8][4];
        #pragma unroll
        for (int kc = 0; kc < 8; ++kc) {
            #pragma unroll
            for (int nbp = 0; nbp < 4; ++nbp) {
                uint32_t bh0, bh1, bh2, bh3;
                LDSM4(bh0, bh1, bh2, bh3, stA + off_h[kc] + nbp * 4096);
                if (kc == 0) {
                    MMA16816_Z(acc[2 * nbp],     ah[kc], bh0, bh1, fzero);
                    MMA16816_Z(acc[2 * nbp + 1], ah[kc], bh2, bh3, fzero);
                } else {
                    MMA16816(acc[2 * nbp],     ah[kc], bh0, bh1);
                    MMA16816(acc[2 * nbp + 1], ah[kc], bh2, bh3);
                }
            }
        }

        // ---- branchless scan: pack idx into mantissa, pair-max, sorted-3 ins
        uint32_t tb = (uint32_t)t << 4;      // bits[4:11) = tile, bits[0:4) = slot
        #pragma unroll
        for (int nb = 0; nb < 8; ++nb) {
            uint32_t s0, s1;
            s0 = (__float_as_uint(acc[nb][0]) & 0xFFFFF800u) | tb | (uint32_t)(nb * 2);
            s1 = (__float_as_uint(acc[nb][1]) & 0xFFFFF800u) | tb | (uint32_t)(nb * 2 + 1);
            ins3(a0, a1, a2, fmaxf(__uint_as_float(s0), __uint_as_float(s1)));
            s0 = (__float_as_uint(acc[nb][2]) & 0xFFFFF800u) | tb | (uint32_t)(nb * 2);
            s1 = (__float_as_uint(acc[nb][3]) & 0xFFFFF800u) | tb | (uint32_t)(nb * 2 + 1);
            ins3(b0_, b1_, b2_, fmaxf(__uint_as_float(s0), __uint_as_float(s1)));
        }

        uint32_t tmp = stA; stA = stB; stB = stC; stC = tmp;
    }

    CP_WAIT(0);

    // ---- decode this lane's packed candidates into (value, index) pairs
    int cb = khalf * 64 + (lane & 3) * 2;   // column base within tile
    float tv0[K8], tv1[K8]; int ti0[K8], ti1[K8];
    {
        float la[3] = { a0, a1, a2 };
        float lb[3] = { b0_, b1_, b2_ };
        #pragma unroll
        for (int r = 0; r < 3; ++r) {
            uint32_t u = __float_as_uint(la[r]);
            int tloc = (int)((u >> 4) & 0x7F);
            int slot = (int)(u & 0xF);
            tv0[r] = la[r];
            ti0[r] = (t0 + tloc) * 128 + cb + (slot >> 1) * 8 + (slot & 1);
            u = __float_as_uint(lb[r]);
            tloc = (int)((u >> 4) & 0x7F);
            slot = (int)(u & 0xF);
            tv1[r] = lb[r];
            ti1[r] = (t0 + tloc) * 128 + cb + (slot >> 1) * 8 + (slot & 1);
        }
        #pragma unroll
        for (int r = 3; r < K8; ++r) {
            tv0[r] = -INFINITY; ti0[r] = -1;
            tv1[r] = -INFINITY; ti1[r] = -1;
        }
    }

    // merge across the 4 lanes sharing each query row -> top-8 per slot
    t8_merge_xor(tv0, ti0, 1); t8_merge_xor(tv0, ti0, 2);
    t8_merge_xor(tv1, ti1, 1); t8_merge_xor(tv1, ti1, 2);

    if ((lane & 3) == 0) {
        int row0 = wq * 16 + (lane >> 2);
        size_t slot = (size_t)((blockIdx.x * NCHUNKS + chunk) * 2 + khalf) * 128;
        size_t b0 = (slot + row0) * K8;
        size_t b1 = (slot + row0 + 8) * K8;
        #pragma unroll
        for (int r = 0; r < K8; ++r) {
            g_pval[b0 + r] = tv0[r]; g_pidx[b0 + r] = ti0[r];
            g_pval[b1 + r] = tv1[r]; g_pidx[b1 + r] = ti1[r];
        }
    }
}

// ---------------- merge + exact rescore + softmax/gather/normalize ----------
__global__ void merge_out(const float* __restrict__ mem, float* __restrict__ out,
                          int N, int B) {
    int q = (blockIdx.x * blockDim.x + threadIdx.x) >> 5;
    int lane = threadIdx.x & 31;
    if (q >= B) return;
    int qtile = q >> 7, ql = q & 127;
    int exq = g_excl[q];

    // ---- phase 1: approx top-RESC of 288 candidates (9 per lane),
    // filtering pad keys (ci >= N) and the exclude index here.
    float cv[9]; int ci[9];
    #pragma unroll
    for (int s = 0; s < 9; ++s) {
        int cidx = lane + 32 * s;                       // < 288 always
        int c = cidx / K8, r = cidx % K8;
        size_t base = ((size_t)(qtile * NSLOTS + c) * 128 + ql) * K8 + r;
        float v = g_pval[base]; int id = g_pidx[base];
        if ((unsigned)id >= (unsigned)N || id == exq) v = -INFINITY;
        cv[s] = v; ci[s] = id;
    }

    int ridx[RESC];
    #pragma unroll
    for (int k = 0; k < RESC; ++k) {
        float bv = cv[0]; int bi = ci[0];
        #pragma unroll
        for (int s = 1; s < 9; ++s)
            if (cv[s] > bv || (cv[s] == bv && ci[s] < bi)) { bv = cv[s]; bi = ci[s]; }
        #pragma unroll
        for (int o = 16; o; o >>= 1) {
            float ov = __shfl_xor_sync(0xffffffffu, bv, o);
            int   oi = __shfl_xor_sync(0xffffffffu, bi, o);
            if (ov > bv || (ov == bv && oi < bi)) { bv = ov; bi = oi; }
        }
        ridx[k] = (bi < 0 || bi >= N) ? 0 : bi;   // safety clamp
        #pragma unroll
        for (int s = 0; s < 9; ++s) if (ci[s] == bi) cv[s] = -INFINITY;
    }

    // ---- phase 2: exact fp32 rescore of the RESC survivors
    float4 qv = *(const float4*)(g_qn + (size_t)q * DIM + lane * 4);
    float rv[RESC];
    #pragma unroll
    for (int k = 0; k < RESC; ++k) {
        float4 m4 = *(const float4*)(mem + (size_t)ridx[k] * DIM + lane * 4);
        float d = qv.x * m4.x + qv.y * m4.y + qv.z * m4.z + qv.w * m4.w;
        #pragma unroll
        for (int o = 16; o; o >>= 1) d += __shfl_xor_sync(0xffffffffu, d, o);
        rv[k] = d;
    }

    // ---- phase 3: exact top-5 (lower index wins ties), all lanes redundant
    float tv[TOPK]; int ti[TOPK];
    int usedmask = 0;
    #pragma unroll
    for (int k = 0; k < TOPK; ++k) {
        float bv = -INFINITY; int bi = 0x7fffffff, bs = -1;
        #pragma unroll
        for (int r = 0; r < RESC; ++r)
            if (!((usedmask >> r) & 1) &&
                (rv[r] > bv || (rv[r] == bv && ridx[r] < bi))) {
                bv = rv[r]; bi = ridx[r]; bs = r;
            }
        usedmask |= 1 << bs;
        tv[k] = bv; ti[k] = bi;
    }

    // ---- softmax over exact top sims
    float e[TOPK], ssum = 0.f;
    #pragma unroll
    for (int k = 0; k < TOPK; ++k) { e[k] = expf((tv[k] - tv[0]) * INV_T); ssum += e[k]; }
    float w[TOPK];
    #pragma unroll
    for (int k = 0; k < TOPK; ++k) w[k] = e[k] / ssum;

    // ---- weighted gather + renormalize
    int d0 = lane * 4;
    float4 a = make_float4(0.f, 0.f, 0.f, 0.f);
    #pragma unroll
    for (int k = 0; k < TOPK; ++k) {
        float4 m4 = *(const float4*)(mem + (size_t)ti[k] * DIM + d0);
        a.x += w[k] * m4.x; a.y += w[k] * m4.y; a.z += w[k] * m4.z; a.w += w[k] * m4.w;
    }
    float ss = a.x * a.x + a.y * a.y + a.z * a.z + a.w * a.w;
    #pragma unroll
    for (int o = 16; o; o >>= 1) ss += __shfl_xor_sync(0xffffffffu, ss, o);
    float sc = 1.0f / fmaxf(sqrtf(ss), 1e-12f);
    float4 r4 = make_float4(a.x * sc, a.y * sc, a.z * sc, a.w * sc);
    *(float4*)(out + (size_t)q * DIM + d0) = r4;

    if (lane == 0) {
        out[(size_t)B * DIM + q] = 1.0f - tv[0];
        #pragma unroll
        for (int k = 0; k < TOPK; ++k)
            out[(size_t)B * DIM + B + (size_t)q * TOPK + k] = w[k];
    }
}

// ---------------- launch ----------------
extern "C" void kernel_launch(void* const* d_in, const int* in_sizes, int n_in,
                              void* d_out, int out_size) {
    const float* query  = (const float*)d_in[0];
    const float* memory = (const float*)d_in[1];
    const void*  excl   = d_in[3];
    int B = in_sizes[0] / DIM;              // 1024
    int N = in_sizes[1] / DIM;              // 200000
    int Ntiles = (N + 127) / 128;           // 1563
    int NPAD = Ntiles * 128;
    float* out = (float*)d_out;

    prep_q<<<(B * 32 + 255) / 256, 256>>>(query, B);
    decode_exclude<<<1, 1024>>>(excl, B);
    split_mem<<<2048, 256>>>(memory, N, NPAD);

    const int SMEM = 3 * 32768 + 1024;      // 99,328 B
    cudaFuncSetAttribute(sim_topk, cudaFuncAttributeMaxDynamicSharedMemorySize, SMEM);
    sim_topk<<<dim3(B / 128, NCHUNKS), 512, SMEM>>>(N, Ntiles);

    merge_out<<<(B * 32 + 255) / 256, 256>>>(memory, out, N, B);
}

// round 10
// speedup vs baseline: 2.2296x; 1.0948x over previous
#include <cuda_runtime.h>
#include <cuda_bf16.h>
#include <math.h>
#include <stdint.h>

// ---------------- problem constants ----------------
#define MAXB     1024
#define DIM      128
#define NCHUNKS  18
#define NSLOTS   (NCHUNKS * 4)     // per-chunk key-quarters
#define PK       4                 // stored candidate depth per slot
#define K8       8                 // merge list depth
#define TOPK     5
#define RESC     10                // rescored candidates per query
#define INV_T    10.0f
#define NPADMAX  (1564 * 128)

// ---------------- device scratch ----------------
__device__ int   g_excl[MAXB];
__device__ float g_qn[MAXB * DIM];                       // normalized queries fp32
__device__ float g_pval[8 * NSLOTS * 128 * PK];
__device__ int   g_pidx[8 * NSLOTS * 128 * PK];
__device__ __nv_bfloat16 g_qh[MAXB * DIM];
__device__ __nv_bfloat16 g_kh[(size_t)NPADMAX * DIM];    // 51.2 MB

// ---------------- PTX helpers ----------------
__device__ __forceinline__ uint32_t smem_u32(const void* p) {
    uint32_t a;
    asm("{ .reg .u64 t; cvta.to.shared.u64 t, %1; cvt.u32.u64 %0, t; }" : "=r"(a) : "l"(p));
    return a;
}
__device__ __forceinline__ void cp16(uint32_t s, const void* g) {
    asm volatile("cp.async.cg.shared.global [%0], [%1], 16;" :: "r"(s), "l"(g));
}
#define CP_COMMIT()  asm volatile("cp.async.commit_group;")
#define CP_WAIT(n)   asm volatile("cp.async.wait_group %0;" :: "n"(n))

#define LDSM4(r0, r1, r2, r3, addr)                                         \
    asm volatile("ldmatrix.sync.aligned.m8n8.x4.shared.b16 {%0,%1,%2,%3}, [%4];" \
                 : "=r"(r0), "=r"(r1), "=r"(r2), "=r"(r3) : "r"(addr))

#define MMA16816(c, a, b0, b1)                                              \
    asm volatile("mma.sync.aligned.m16n8k16.row.col.f32.bf16.bf16.f32 "     \
                 "{%0,%1,%2,%3},{%4,%5,%6,%7},{%8,%9},{%0,%1,%2,%3};"       \
                 : "+f"((c)[0]), "+f"((c)[1]), "+f"((c)[2]), "+f"((c)[3])   \
                 : "r"((a)[0]), "r"((a)[1]), "r"((a)[2]), "r"((a)[3]),      \
                   "r"(b0), "r"(b1))

// first-k MMA: D = A*B + 0 (separate zero C input; kills acc-init MOVs)
#define MMA16816_Z(c, a, b0, b1, zr)                                        \
    asm volatile("mma.sync.aligned.m16n8k16.row.col.f32.bf16.bf16.f32 "     \
                 "{%0,%1,%2,%3},{%4,%5,%6,%7},{%8,%9},{%10,%10,%10,%10};"   \
                 : "=f"((c)[0]), "=f"((c)[1]), "=f"((c)[2]), "=f"((c)[3])   \
                 : "r"((a)[0]), "r"((a)[1]), "r"((a)[2]), "r"((a)[3]),      \
                   "r"(b0), "r"(b1), "f"(zr))

// ---------------- branchless sorted-3 insert (5 FMNMX, no indices) --------
__device__ __forceinline__ void ins3(float &a, float &b, float &c, float x) {
    float m;
    m = fmaxf(a, x); x = fminf(a, x); a = m;
    m = fmaxf(b, x); x = fminf(b, x); b = m;
    c = fmaxf(c, x);
}

// ---------------- top-8 (value,idx) helpers for the endgame merge ----------
__device__ __forceinline__ void t8_ins(float (&tv)[K8], int (&ti)[K8], float s, int idx) {
    tv[K8 - 1] = s; ti[K8 - 1] = idx;
    #pragma unroll
    for (int p = K8 - 1; p > 0; --p) {
        if (tv[p] > tv[p - 1]) {
            float fv = tv[p]; tv[p] = tv[p - 1]; tv[p - 1] = fv;
            int fi = ti[p]; ti[p] = ti[p - 1]; ti[p - 1] = fi;
        }
    }
}
__device__ __forceinline__ void t8_merge_xor(float (&tv)[K8], int (&ti)[K8], int off) {
    float pv[K8]; int pi[K8];
    #pragma unroll
    for (int r = 0; r < K8; ++r) {
        pv[r] = __shfl_xor_sync(0xffffffffu, tv[r], off);
        pi[r] = __shfl_xor_sync(0xffffffffu, ti[r], off);
    }
    #pragma unroll
    for (int r = 0; r < K8; ++r)
        if (pv[r] > tv[K8 - 1]) t8_ins(tv, ti, pv[r], pi[r]);
}

// ---------------- kernel: normalize queries (fp32 + bf16-hi) ----------------
__global__ void prep_q(const float* __restrict__ q, int B) {
    int w = (blockIdx.x * blockDim.x + threadIdx.x) >> 5;
    int lane = threadIdx.x & 31;
    if (w >= B) return;
    float4 v = *(const float4*)(q + (size_t)w * DIM + lane * 4);
    float ss = v.x * v.x + v.y * v.y + v.z * v.z + v.w * v.w;
    #pragma unroll
    for (int o = 16; o; o >>= 1) ss += __shfl_xor_sync(0xffffffffu, ss, o);
    float sc = 1.0f / fmaxf(sqrtf(ss), 1e-12f);
    float4 r = make_float4(v.x * sc, v.y * sc, v.z * sc, v.w * sc);
    size_t off = (size_t)w * DIM + lane * 4;
    *(float4*)(g_qn + off) = r;
    __nv_bfloat162 h0 = __floats2bfloat162_rn(r.x, r.y);
    __nv_bfloat162 h1 = __floats2bfloat162_rn(r.z, r.w);
    *(uint2*)(g_qh + off) = make_uint2(*(uint32_t*)&h0, *(uint32_t*)&h1);
}

// ---------------- kernel: decode exclude (int32/int64 sniff) ----------------
__global__ void decode_exclude(const void* __restrict__ ex, int B) {
    __shared__ int nz;
    int t = threadIdx.x;
    if (t == 0) nz = 0;
    __syncthreads();
    const int* e32 = (const int*)ex;
    if (t < B / 2) { if (e32[2 * t + 1] != 0) atomicAdd(&nz, 1); }
    __syncthreads();
    bool is64 = (nz == 0);
    if (t < B) {
        long long v = is64 ? ((const long long*)ex)[t] : (long long)e32[t];
        g_excl[t] = (int)v;
    }
}

// ---------------- kernel: fp32 memory -> bf16 hi ----------------
__global__ void split_mem(const float* __restrict__ mem, int N, int NPAD) {
    int total4 = NPAD * (DIM / 4);
    for (int i = blockIdx.x * blockDim.x + threadIdx.x; i < total4;
         i += gridDim.x * blockDim.x) {
        int row = i >> 5;
        float4 v = make_float4(0.f, 0.f, 0.f, 0.f);
        if (row < N) v = ((const float4*)mem)[i];
        __nv_bfloat162 h0 = __floats2bfloat162_rn(v.x, v.y);
        __nv_bfloat162 h1 = __floats2bfloat162_rn(v.z, v.w);
        ((uint2*)g_kh)[i] = make_uint2(*(uint32_t*)&h0, *(uint32_t*)&h1);
    }
}

// ---------------- key tile loader (XOR-swizzled rows for ldmatrix) ----------
__device__ __forceinline__ void load_ktile(uint32_t stage_u, int key0, bool valid, int tid) {
    if (valid) {
        #pragma unroll
        for (int c = tid; c < 2048; c += 512) {
            int row = c >> 4, ch = c & 15;
            uint32_t off = (uint32_t)(row * 256 + (((ch ^ (row & 7))) << 4));
            cp16(stage_u + off, g_kh + (size_t)(key0 + row) * DIM + ch * 8);
        }
    }
    CP_COMMIT();
}

// ---------------- main filter kernel ----------------
__global__ void __launch_bounds__(512, 1)
sim_topk(int N, int Ntiles) {
    extern __shared__ __align__(16) char sm[];
    uint32_t smb = smem_u32(sm);
    uint32_t stage_u = (smb + 1023u) & ~1023u;

    int tid = threadIdx.x;
    int wid = tid >> 5;
    int lane = tid & 31;
    int wq = wid & 3;            // query-row group (32 rows)
    int kq = wid >> 2;           // key quarter (32 keys)
    int qbase = blockIdx.x * 128;
    int chunk = blockIdx.y;

    int TPC = (Ntiles + NCHUNKS - 1) / NCHUNKS;   // 87 (< 128, fits 7 bits)
    int t0 = chunk * TPC;
    int T = min(TPC, Ntiles - t0); if (T < 0) T = 0;

    load_ktile(stage_u,         (t0 + 0) * 128, 0 < T, tid);
    load_ktile(stage_u + 32768, (t0 + 1) * 128, 1 < T, tid);

    // preload A fragments: this warp's 32 query rows = 2 m16 blocks
    int qr = qbase + wq * 32 + (lane >> 2);
    uint32_t ah[8][8];           // [kc][m*4 + j]
    #pragma unroll
    for (int kc = 0; kc < 8; ++kc) {
        int c = kc * 16 + (lane & 3) * 2;
        #pragma unroll
        for (int m = 0; m < 2; ++m) {
            const __nv_bfloat16* qp = g_qh + (size_t)(qr + m * 16) * DIM;
            ah[kc][m * 4 + 0] = *(const uint32_t*)(qp + c);
            ah[kc][m * 4 + 1] = *(const uint32_t*)(qp + 8 * DIM + c);
            ah[kc][m * 4 + 2] = *(const uint32_t*)(qp + c + 8);
            ah[kc][m * 4 + 3] = *(const uint32_t*)(qp + 8 * DIM + c + 8);
        }
    }

    // 4 per-lane top-3 lists (rows +0,+8,+16,+24), idx packed in low 10 bits
    float lv[4][3];
    #pragma unroll
    for (int l = 0; l < 4; ++l)
        lv[l][0] = lv[l][1] = lv[l][2] = -3.0e38f;

    int r_   = lane & 7;
    int cbit = (lane >> 3) & 1;
    int kb256 = (kq << 13) + ((lane >> 4) * 8 + r_) * 256;

    // precompute swizzled LDSM offsets (constant across tiles)
    uint32_t off_h[8];
    #pragma unroll
    for (int kc = 0; kc < 8; ++kc)
        off_h[kc] = (uint32_t)kb256 + (uint32_t)(((kc * 2 + cbit) ^ r_) << 4);

    uint32_t stA = stage_u, stB = stage_u + 32768, stC = stage_u + 65536;
    const float fzero = 0.0f;

    for (int t = 0; t < T; ++t) {
        CP_WAIT(1);
        __syncthreads();

        load_ktile(stC, (t0 + t + 2) * 128, (t + 2) < T, tid);

        #pragma unroll
        for (int nbp = 0; nbp < 2; ++nbp) {
            float acc[2][2][4];              // [m][n][j]
            #pragma unroll
            for (int kc = 0; kc < 8; ++kc) {
                uint32_t bh0, bh1, bh2, bh3;
                LDSM4(bh0, bh1, bh2, bh3, stA + off_h[kc] + nbp * 4096);
                if (kc == 0) {
                    MMA16816_Z(acc[0][0], (&ah[kc][0]), bh0, bh1, fzero);
                    MMA16816_Z(acc[0][1], (&ah[kc][0]), bh2, bh3, fzero);
                    MMA16816_Z(acc[1][0], (&ah[kc][4]), bh0, bh1, fzero);
                    MMA16816_Z(acc[1][1], (&ah[kc][4]), bh2, bh3, fzero);
                } else {
                    MMA16816(acc[0][0], (&ah[kc][0]), bh0, bh1);
                    MMA16816(acc[0][1], (&ah[kc][0]), bh2, bh3);
                    MMA16816(acc[1][0], (&ah[kc][4]), bh0, bh1);
                    MMA16816(acc[1][1], (&ah[kc][4]), bh2, bh3);
                }
            }

            // scan these 16 values now (interleaves with next nbp's MMAs)
            uint32_t tb = ((uint32_t)t << 3) | ((uint32_t)nbp << 2);
            #pragma unroll
            for (int m = 0; m < 2; ++m) {
                #pragma unroll
                for (int n = 0; n < 2; ++n) {
                    uint32_t meta = tb | ((uint32_t)n << 1);
                    uint32_t s0, s1;
                    // row (lane>>2): acc[m][n][0..1]
                    s0 = (__float_as_uint(acc[m][n][0]) & 0xFFFFFC00u) | meta;
                    s1 = (__float_as_uint(acc[m][n][1]) & 0xFFFFFC00u) | meta | 1u;
                    ins3(lv[m * 2][0], lv[m * 2][1], lv[m * 2][2],
                         fmaxf(__uint_as_float(s0), __uint_as_float(s1)));
                    // row (lane>>2)+8: acc[m][n][2..3]
                    s0 = (__float_as_uint(acc[m][n][2]) & 0xFFFFFC00u) | meta;
                    s1 = (__float_as_uint(acc[m][n][3]) & 0xFFFFFC00u) | meta | 1u;
                    ins3(lv[m * 2 + 1][0], lv[m * 2 + 1][1], lv[m * 2 + 1][2],
                         fmaxf(__uint_as_float(s0), __uint_as_float(s1)));
                }
            }
        }

        uint32_t tmp = stA; stA = stB; stB = stC; stC = tmp;
    }

    CP_WAIT(0);

    // ---- decode packed candidates, merge across the 4 lanes per row ----
    int cb = kq * 32 + (lane & 3) * 2;   // key base within tile
    #pragma unroll
    for (int l = 0; l < 4; ++l) {
        float tv[K8]; int ti[K8];
        #pragma unroll
        for (int r = 0; r < 3; ++r) {
            uint32_t u = __float_as_uint(lv[l][r]);
            tv[r] = lv[l][r];
            ti[r] = (t0 + (int)((u >> 3) & 0x7F)) * 128 + cb +
                    (int)((u >> 2) & 1) * 16 + (int)((u >> 1) & 1) * 8 + (int)(u & 1);
        }
        #pragma unroll
        for (int r = 3; r < K8; ++r) { tv[r] = -INFINITY; ti[r] = -1; }

        t8_merge_xor(tv, ti, 1);
        t8_merge_xor(tv, ti, 2);

        if ((lane & 3) == 0) {
            int row = wq * 32 + (lane >> 2) + l * 8;
            size_t slotbase = (size_t)((blockIdx.x * NCHUNKS + chunk) * 4 + kq) * 128;
            size_t b = (slotbase + row) * PK;
            #pragma unroll
            for (int r = 0; r < PK; ++r) { g_pval[b + r] = tv[r]; g_pidx[b + r] = ti[r]; }
        }
    }
}

// ---------------- merge + exact rescore + softmax/gather/normalize ----------
__global__ void merge_out(const float* __restrict__ mem, float* __restrict__ out,
                          int N, int B) {
    int q = (blockIdx.x * blockDim.x + threadIdx.x) >> 5;
    int lane = threadIdx.x & 31;
    if (q >= B) return;
    int qtile = q >> 7, ql = q & 127;
    int exq = g_excl[q];

    // ---- phase 1: approx top-RESC of 288 candidates (9 per lane),
    // filtering pad keys (ci >= N) and the exclude index here.
    float cv[9]; int ci[9];
    #pragma unroll
    for (int s = 0; s < 9; ++s) {
        int cidx = lane + 32 * s;                       // < 288 always
        int c = cidx >> 2, r = cidx & 3;
        size_t base = ((size_t)(qtile * NSLOTS + c) * 128 + ql) * PK + r;
        float v = g_pval[base]; int id = g_pidx[base];
        if ((unsigned)id >= (unsigned)N || id == exq) v = -INFINITY;
        cv[s] = v; ci[s] = id;
    }

    int ridx[RESC];
    #pragma unroll
    for (int k = 0; k < RESC; ++k) {
        float bv = cv[0]; int bi = ci[0];
        #pragma unroll
        for (int s = 1; s < 9; ++s)
            if (cv[s] > bv || (cv[s] == bv && ci[s] < bi)) { bv = cv[s]; bi = ci[s]; }
        #pragma unroll
        for (int o = 16; o; o >>= 1) {
            float ov = __shfl_xor_sync(0xffffffffu, bv, o);
            int   oi = __shfl_xor_sync(0xffffffffu, bi, o);
            if (ov > bv || (ov == bv && oi < bi)) { bv = ov; bi = oi; }
        }
        ridx[k] = (bi < 0 || bi >= N) ? 0 : bi;   // safety clamp
        #pragma unroll
        for (int s = 0; s < 9; ++s) if (ci[s] == bi) cv[s] = -INFINITY;
    }

    // ---- phase 2: exact fp32 rescore of the RESC survivors
    float4 qv = *(const float4*)(g_qn + (size_t)q * DIM + lane * 4);
    float rv[RESC];
    #pragma unroll
    for (int k = 0; k < RESC; ++k) {
        float4 m4 = *(const float4*)(mem + (size_t)ridx[k] * DIM + lane * 4);
        float d = qv.x * m4.x + qv.y * m4.y + qv.z * m4.z + qv.w * m4.w;
        #pragma unroll
        for (int o = 16; o; o >>= 1) d += __shfl_xor_sync(0xffffffffu, d, o);
        rv[k] = d;
    }

    // ---- phase 3: exact top-5 (lower index wins ties), all lanes redundant
    float tv[TOPK]; int ti[TOPK];
    int usedmask = 0;
    #pragma unroll
    for (int k = 0; k < TOPK; ++k) {
        float bv = -INFINITY; int bi = 0x7fffffff, bs = -1;
        #pragma unroll
        for (int r = 0; r < RESC; ++r)
            if (!((usedmask >> r) & 1) &&
                (rv[r] > bv || (rv[r] == bv && ridx[r] < bi))) {
                bv = rv[r]; bi = ridx[r]; bs = r;
            }
        usedmask |= 1 << bs;
        tv[k] = bv; ti[k] = bi;
    }

    // ---- softmax over exact top sims
    float e[TOPK], ssum = 0.f;
    #pragma unroll
    for (int k = 0; k < TOPK; ++k) { e[k] = expf((tv[k] - tv[0]) * INV_T); ssum += e[k]; }
    float w[TOPK];
    #pragma unroll
    for (int k = 0; k < TOPK; ++k) w[k] = e[k] / ssum;

    // ---- weighted gather + renormalize
    int d0 = lane * 4;
    float4 a = make_float4(0.f, 0.f, 0.f, 0.f);
    #pragma unroll
    for (int k = 0; k < TOPK; ++k) {
        float4 m4 = *(const float4*)(mem + (size_t)ti[k] * DIM + d0);
        a.x += w[k] * m4.x; a.y += w[k] * m4.y; a.z += w[k] * m4.z; a.w += w[k] * m4.w;
    }
    float ss = a.x * a.x + a.y * a.y + a.z * a.z + a.w * a.w;
    #pragma unroll
    for (int o = 16; o; o >>= 1) ss += __shfl_xor_sync(0xffffffffu, ss, o);
    float sc = 1.0f / fmaxf(sqrtf(ss), 1e-12f);
    float4 r4 = make_float4(a.x * sc, a.y * sc, a.z * sc, a.w * sc);
    *(float4*)(out + (size_t)q * DIM + d0) = r4;

    if (lane == 0) {
        out[(size_t)B * DIM + q] = 1.0f - tv[0];
        #pragma unroll
        for (int k = 0; k < TOPK; ++k)
            out[(size_t)B * DIM + B + (size_t)q * TOPK + k] = w[k];
    }
}

// ---------------- launch ----------------
extern "C" void kernel_launch(void* const* d_in, const int* in_sizes, int n_in,
                              void* d_out, int out_size) {
    const float* query  = (const float*)d_in[0];
    const float* memory = (const float*)d_in[1];
    const void*  excl   = d_in[3];
    int B = in_sizes[0] / DIM;              // 1024
    int N = in_sizes[1] / DIM;              // 200000
    int Ntiles = (N + 127) / 128;           // 1563
    int NPAD = Ntiles * 128;
    float* out = (float*)d_out;

    prep_q<<<(B * 32 + 255) / 256, 256>>>(query, B);
    decode_exclude<<<1, 1024>>>(excl, B);
    split_mem<<<2048, 256>>>(memory, N, NPAD);

    const int SMEM = 3 * 32768 + 1024;      // 99,328 B
    cudaFuncSetAttribute(sim_topk, cudaFuncAttributeMaxDynamicSharedMemorySize, SMEM);
    sim_topk<<<dim3(B / 128, NCHUNKS), 512, SMEM>>>(N, Ntiles);

    merge_out<<<(B * 32 + 255) / 256, 256>>>(memory, out, N, B);
}